// round 3
// baseline (speedup 1.0000x reference)
#include <cuda_runtime.h>
#include <cuda_bf16.h>
#include <math.h>

#define D_MODEL 1024
#define NHEAD   16
#define HDIM    64
#define SEQ     2048
#define BATCH   2
#define MTOT    (BATCH * SEQ)   // 4096

// ---------------- scratch (static device globals: allocation-free) ----------
__device__ float g_Q[BATCH * NHEAD * SEQ * HDIM];  // 16 MB, [b,h,s,d]
__device__ float g_K[BATCH * NHEAD * SEQ * HDIM];
__device__ float g_V[BATCH * NHEAD * SEQ * HDIM];
__device__ float g_A[MTOT * D_MODEL];              // attn output, [b,s, h*64+d]

// ---------------------------------------------------------------------------
// C = A * B^T.  A:[M,K] row-major, B:[N,K] row-major (torch Linear weight).
// 128x128 block tile, K-step 8, double-buffered smem, 256 threads, 8x8/thread.
// mode 0: C[m*N + n]   (plain row-major)
// mode 1: scatter to [b, h, s, d] layout (n = h*64 + d, m = b*2048 + s)
// ---------------------------------------------------------------------------
__global__ __launch_bounds__(256) void sgemm_nt(
    const float* __restrict__ A, const float* __restrict__ B,
    float* __restrict__ C, int K, int N, int mode)
{
    __shared__ __align__(16) float As[2][8][128];
    __shared__ __align__(16) float Bs[2][8][128];

    const int tid  = threadIdx.x;
    const int bm   = blockIdx.y * 128;
    const int bn   = blockIdx.x * 128;
    const int lrow = tid >> 1;           // 0..127
    const int lcol = (tid & 1) * 4;      // 0 or 4

    const float* Ap = A + (bm + lrow) * K + lcol;
    const float* Bp = B + (bn + lrow) * K + lcol;

    // preload tile 0
    {
        float4 av = *(const float4*)Ap;
        float4 bv = *(const float4*)Bp;
        As[0][lcol + 0][lrow] = av.x; As[0][lcol + 1][lrow] = av.y;
        As[0][lcol + 2][lrow] = av.z; As[0][lcol + 3][lrow] = av.w;
        Bs[0][lcol + 0][lrow] = bv.x; Bs[0][lcol + 1][lrow] = bv.y;
        Bs[0][lcol + 2][lrow] = bv.z; Bs[0][lcol + 3][lrow] = bv.w;
    }
    __syncthreads();

    const int tx = tid & 15;   // N direction
    const int ty = tid >> 4;   // M direction

    float acc[8][8];
#pragma unroll
    for (int i = 0; i < 8; ++i)
#pragma unroll
        for (int j = 0; j < 8; ++j) acc[i][j] = 0.0f;

    int buf = 0;
    for (int k0 = 8;; k0 += 8) {
        const bool more = (k0 < K);
        float4 av2, bv2;
        if (more) {
            av2 = *(const float4*)(Ap + k0);
            bv2 = *(const float4*)(Bp + k0);
        }
#pragma unroll
        for (int kk = 0; kk < 8; ++kk) {
            float a[8], b[8];
            float4 t;
            t = *(const float4*)&As[buf][kk][ty * 8];     a[0]=t.x; a[1]=t.y; a[2]=t.z; a[3]=t.w;
            t = *(const float4*)&As[buf][kk][ty * 8 + 4]; a[4]=t.x; a[5]=t.y; a[6]=t.z; a[7]=t.w;
            t = *(const float4*)&Bs[buf][kk][tx * 8];     b[0]=t.x; b[1]=t.y; b[2]=t.z; b[3]=t.w;
            t = *(const float4*)&Bs[buf][kk][tx * 8 + 4]; b[4]=t.x; b[5]=t.y; b[6]=t.z; b[7]=t.w;
#pragma unroll
            for (int i = 0; i < 8; ++i)
#pragma unroll
                for (int j = 0; j < 8; ++j)
                    acc[i][j] += a[i] * b[j];
        }
        if (!more) break;
        const int nb = buf ^ 1;
        As[nb][lcol + 0][lrow] = av2.x; As[nb][lcol + 1][lrow] = av2.y;
        As[nb][lcol + 2][lrow] = av2.z; As[nb][lcol + 3][lrow] = av2.w;
        Bs[nb][lcol + 0][lrow] = bv2.x; Bs[nb][lcol + 1][lrow] = bv2.y;
        Bs[nb][lcol + 2][lrow] = bv2.z; Bs[nb][lcol + 3][lrow] = bv2.w;
        __syncthreads();
        buf = nb;
    }

    if (mode == 0) {
#pragma unroll
        for (int i = 0; i < 8; ++i) {
            const int row = bm + ty * 8 + i;
            float* cp = C + row * N + bn + tx * 8;
            *(float4*)(cp)     = make_float4(acc[i][0], acc[i][1], acc[i][2], acc[i][3]);
            *(float4*)(cp + 4) = make_float4(acc[i][4], acc[i][5], acc[i][6], acc[i][7]);
        }
    } else {
#pragma unroll
        for (int i = 0; i < 8; ++i) {
            const int m  = bm + ty * 8 + i;
            const int bb = m >> 11;       // / 2048
            const int s  = m & 2047;
#pragma unroll
            for (int jg = 0; jg < 8; jg += 4) {
                const int n0 = bn + tx * 8 + jg;   // multiple of 4, never straddles head
                const int h  = n0 >> 6;
                const int d  = n0 & 63;
                float* cp = C + (((bb * NHEAD + h) * SEQ + s) * HDIM + d);
                *(float4*)cp = make_float4(acc[i][jg], acc[i][jg + 1],
                                           acc[i][jg + 2], acc[i][jg + 3]);
            }
        }
    }
}

// ---------------------------------------------------------------------------
// Flash attention, fp32, causal.  One block = 64 queries of one (b,h).
// 256 threads as 16x16.  Online softmax; stats replicated in registers across
// each 16-lane row group (deterministic shfl reductions keep them consistent).
// smem (dynamic, 64 KB): Qs[64][64], Kt[64][64] (d-major!), Vs[64][64], Ps[64][64]
// ---------------------------------------------------------------------------
__global__ __launch_bounds__(256) void attn_kernel(
    float* __restrict__ Aout,
    const float* __restrict__ Qg, const float* __restrict__ Kg,
    const float* __restrict__ Vg)
{
    extern __shared__ float sm[];
    float* Qs = sm;             // [q][d]
    float* Kt = sm + 4096;      // [d][k]   transposed -> conflict-free S reads
    float* Vs = sm + 8192;      // [k][d]
    float* Ps = sm + 12288;     // [q][k]

    const int tid = threadIdx.x;
    const int tx  = tid & 15;
    const int ty  = tid >> 4;
    const int bh  = blockIdx.y;           // b*16 + h
    const int qt  = blockIdx.x;           // q tile index

    const float* Qp = Qg + (bh * SEQ + qt * 64) * HDIM;

    // load Q tile, pre-scaled by 1/sqrt(64)
#pragma unroll
    for (int p = 0; p < 4; ++p) {
        const int idx = tid * 4 + p * 1024;
        float4 v = *(const float4*)(Qp + idx);
        v.x *= 0.125f; v.y *= 0.125f; v.z *= 0.125f; v.w *= 0.125f;
        *(float4*)(Qs + idx) = v;
    }

    float o[4][4];
    float m_r[4], l_r[4];
#pragma unroll
    for (int i = 0; i < 4; ++i) {
        m_r[i] = -1e30f; l_r[i] = 0.0f;
#pragma unroll
        for (int j = 0; j < 4; ++j) o[i][j] = 0.0f;
    }

    for (int kt = 0; kt <= qt; ++kt) {
        const float* Kp = Kg + (bh * SEQ + kt * 64) * HDIM;
        const float* Vp = Vg + (bh * SEQ + kt * 64) * HDIM;

        __syncthreads();   // previous iteration's Ps/Vs reads done

        // K tile -> smem transposed: Kt[d][k]
        {
            const int kr = tid >> 2;
            const int d0 = (tid & 3) * 16;
#pragma unroll
            for (int c = 0; c < 16; c += 4) {
                float4 v = *(const float4*)(Kp + kr * 64 + d0 + c);
                Kt[(d0 + c + 0) * 64 + kr] = v.x;
                Kt[(d0 + c + 1) * 64 + kr] = v.y;
                Kt[(d0 + c + 2) * 64 + kr] = v.z;
                Kt[(d0 + c + 3) * 64 + kr] = v.w;
            }
        }
        // V tile -> smem natural layout
#pragma unroll
        for (int p = 0; p < 4; ++p) {
            const int idx = tid * 4 + p * 1024;
            *(float4*)(Vs + idx) = *(const float4*)(Vp + idx);
        }
        __syncthreads();

        // ---- S = Q K^T (this thread: rows ty*4+i, cols tx*4+j) ----
        float s[4][4];
#pragma unroll
        for (int i = 0; i < 4; ++i)
#pragma unroll
            for (int j = 0; j < 4; ++j) s[i][j] = 0.0f;

#pragma unroll 4
        for (int d = 0; d < 64; d += 4) {
            float kk[4][4];
#pragma unroll
            for (int dd = 0; dd < 4; ++dd) {
                float4 t = *(const float4*)(Kt + (d + dd) * 64 + tx * 4);
                kk[dd][0] = t.x; kk[dd][1] = t.y; kk[dd][2] = t.z; kk[dd][3] = t.w;
            }
#pragma unroll
            for (int i = 0; i < 4; ++i) {
                float4 t = *(const float4*)(Qs + (ty * 4 + i) * 64 + d);
#pragma unroll
                for (int j = 0; j < 4; ++j)
                    s[i][j] += t.x * kk[0][j] + t.y * kk[1][j]
                             + t.z * kk[2][j] + t.w * kk[3][j];
            }
        }

        // causal mask on the diagonal tile
        if (kt == qt) {
#pragma unroll
            for (int i = 0; i < 4; ++i)
#pragma unroll
                for (int j = 0; j < 4; ++j)
                    if (tx * 4 + j > ty * 4 + i) s[i][j] = -1e30f;
        }

        // ---- online softmax update ----
#pragma unroll
        for (int i = 0; i < 4; ++i) {
            float rm = fmaxf(fmaxf(s[i][0], s[i][1]), fmaxf(s[i][2], s[i][3]));
#pragma unroll
            for (int off = 8; off >= 1; off >>= 1)
                rm = fmaxf(rm, __shfl_xor_sync(0xffffffffu, rm, off));
            const float mn = fmaxf(m_r[i], rm);
            const float p0 = __expf(s[i][0] - mn);
            const float p1 = __expf(s[i][1] - mn);
            const float p2 = __expf(s[i][2] - mn);
            const float p3 = __expf(s[i][3] - mn);
            float rs = (p0 + p1) + (p2 + p3);
#pragma unroll
            for (int off = 8; off >= 1; off >>= 1)
                rs += __shfl_xor_sync(0xffffffffu, rs, off);
            const float f = __expf(m_r[i] - mn);
            l_r[i] = l_r[i] * f + rs;
            m_r[i] = mn;
            o[i][0] *= f; o[i][1] *= f; o[i][2] *= f; o[i][3] *= f;
            *(float4*)(Ps + (ty * 4 + i) * 64 + tx * 4) = make_float4(p0, p1, p2, p3);
        }
        __syncthreads();

        // ---- O += P V (this thread: rows ty*4+i, dims tx*4+j) ----
#pragma unroll 4
        for (int k = 0; k < 64; k += 4) {
            float pv[4][4], vv[4][4];
#pragma unroll
            for (int i = 0; i < 4; ++i) {
                float4 t = *(const float4*)(Ps + (ty * 4 + i) * 64 + k);
                pv[i][0] = t.x; pv[i][1] = t.y; pv[i][2] = t.z; pv[i][3] = t.w;
            }
#pragma unroll
            for (int c = 0; c < 4; ++c) {
                float4 t = *(const float4*)(Vs + (k + c) * 64 + tx * 4);
                vv[c][0] = t.x; vv[c][1] = t.y; vv[c][2] = t.z; vv[c][3] = t.w;
            }
#pragma unroll
            for (int i = 0; i < 4; ++i)
#pragma unroll
                for (int j = 0; j < 4; ++j)
                    o[i][j] += pv[i][0] * vv[0][j] + pv[i][1] * vv[1][j]
                             + pv[i][2] * vv[2][j] + pv[i][3] * vv[3][j];
        }
    }

    // epilogue: normalize and write to [b, s, h*64 + d]
    const int b = bh >> 4;
    const int h = bh & 15;
#pragma unroll
    for (int i = 0; i < 4; ++i) {
        const float inv = 1.0f / l_r[i];
        const int row = b * SEQ + qt * 64 + ty * 4 + i;
        float* op = Aout + row * D_MODEL + h * HDIM + tx * 4;
        *(float4*)op = make_float4(o[i][0] * inv, o[i][1] * inv,
                                   o[i][2] * inv, o[i][3] * inv);
    }
}

// ---------------------------------------------------------------------------
extern "C" void kernel_launch(void* const* d_in, const int* in_sizes, int n_in,
                              void* d_out, int out_size)
{
    const float* x  = (const float*)d_in[0];
    const float* Wq = (const float*)d_in[1];
    const float* Wk = (const float*)d_in[2];
    const float* Wv = (const float*)d_in[3];
    const float* Wo = (const float*)d_in[4];
    float* out = (float*)d_out;

    float *q, *k, *v, *a;
    cudaGetSymbolAddress((void**)&q, g_Q);
    cudaGetSymbolAddress((void**)&k, g_K);
    cudaGetSymbolAddress((void**)&v, g_V);
    cudaGetSymbolAddress((void**)&a, g_A);

    const dim3 gg(D_MODEL / 128, MTOT / 128);   // (8, 32)

    sgemm_nt<<<gg, 256>>>(x, Wq, q, D_MODEL, D_MODEL, 1);
    sgemm_nt<<<gg, 256>>>(x, Wk, k, D_MODEL, D_MODEL, 1);
    sgemm_nt<<<gg, 256>>>(x, Wv, v, D_MODEL, D_MODEL, 1);

    cudaFuncSetAttribute(attn_kernel,
                         cudaFuncAttributeMaxDynamicSharedMemorySize, 65536);
    attn_kernel<<<dim3(SEQ / 64, BATCH * NHEAD), 256, 65536>>>(a, q, k, v);

    sgemm_nt<<<gg, 256>>>(a, Wo, out, D_MODEL, D_MODEL, 0);
}

// round 4
// speedup vs baseline: 1.0016x; 1.0016x over previous
#include <cuda_runtime.h>
#include <cuda_bf16.h>
#include <math.h>

#define D_MODEL 1024
#define NHEAD   16
#define HDIM    64
#define SEQ     2048
#define BATCH   2
#define MTOT    (BATCH * SEQ)   // 4096

// ---------------- scratch (static device globals: allocation-free) ----------
__device__ float g_Q[BATCH * NHEAD * SEQ * HDIM];  // 16 MB, [b,h,s,d]
__device__ float g_K[BATCH * NHEAD * SEQ * HDIM];
__device__ float g_V[BATCH * NHEAD * SEQ * HDIM];
__device__ float g_A[MTOT * D_MODEL];              // attn output, [b,s, h*64+d]

// ---------------------------------------------------------------------------
// C = A * B^T.  A:[M,K] row-major, B:[N,K] row-major (torch Linear weight).
// 128x128 block tile, K-step 8, double-buffered smem, 256 threads, 8x8/thread.
// mode 0: C[m*N + n]   (plain row-major)
// mode 1: scatter to [b, h, s, d] layout (n = h*64 + d, m = b*2048 + s)
// ---------------------------------------------------------------------------
__global__ __launch_bounds__(256) void sgemm_nt(
    const float* __restrict__ A, const float* __restrict__ B,
    float* __restrict__ C, int K, int N, int mode)
{
    __shared__ __align__(16) float As[2][8][128];
    __shared__ __align__(16) float Bs[2][8][128];

    const int tid  = threadIdx.x;
    const int bm   = blockIdx.y * 128;
    const int bn   = blockIdx.x * 128;
    const int lrow = tid >> 1;           // 0..127
    const int lcol = (tid & 1) * 4;      // 0 or 4

    const float* Ap = A + (bm + lrow) * K + lcol;
    const float* Bp = B + (bn + lrow) * K + lcol;

    // preload tile 0
    {
        float4 av = *(const float4*)Ap;
        float4 bv = *(const float4*)Bp;
        As[0][lcol + 0][lrow] = av.x; As[0][lcol + 1][lrow] = av.y;
        As[0][lcol + 2][lrow] = av.z; As[0][lcol + 3][lrow] = av.w;
        Bs[0][lcol + 0][lrow] = bv.x; Bs[0][lcol + 1][lrow] = bv.y;
        Bs[0][lcol + 2][lrow] = bv.z; Bs[0][lcol + 3][lrow] = bv.w;
    }
    __syncthreads();

    const int tx = tid & 15;   // N direction
    const int ty = tid >> 4;   // M direction

    float acc[8][8];
#pragma unroll
    for (int i = 0; i < 8; ++i)
#pragma unroll
        for (int j = 0; j < 8; ++j) acc[i][j] = 0.0f;

    int buf = 0;
    for (int k0 = 8;; k0 += 8) {
        const bool more = (k0 < K);
        float4 av2, bv2;
        if (more) {
            av2 = *(const float4*)(Ap + k0);
            bv2 = *(const float4*)(Bp + k0);
        }
#pragma unroll
        for (int kk = 0; kk < 8; ++kk) {
            float a[8], b[8];
            float4 t;
            t = *(const float4*)&As[buf][kk][ty * 8];     a[0]=t.x; a[1]=t.y; a[2]=t.z; a[3]=t.w;
            t = *(const float4*)&As[buf][kk][ty * 8 + 4]; a[4]=t.x; a[5]=t.y; a[6]=t.z; a[7]=t.w;
            t = *(const float4*)&Bs[buf][kk][tx * 8];     b[0]=t.x; b[1]=t.y; b[2]=t.z; b[3]=t.w;
            t = *(const float4*)&Bs[buf][kk][tx * 8 + 4]; b[4]=t.x; b[5]=t.y; b[6]=t.z; b[7]=t.w;
#pragma unroll
            for (int i = 0; i < 8; ++i)
#pragma unroll
                for (int j = 0; j < 8; ++j)
                    acc[i][j] += a[i] * b[j];
        }
        if (!more) break;
        const int nb = buf ^ 1;
        As[nb][lcol + 0][lrow] = av2.x; As[nb][lcol + 1][lrow] = av2.y;
        As[nb][lcol + 2][lrow] = av2.z; As[nb][lcol + 3][lrow] = av2.w;
        Bs[nb][lcol + 0][lrow] = bv2.x; Bs[nb][lcol + 1][lrow] = bv2.y;
        Bs[nb][lcol + 2][lrow] = bv2.z; Bs[nb][lcol + 3][lrow] = bv2.w;
        __syncthreads();
        buf = nb;
    }

    if (mode == 0) {
#pragma unroll
        for (int i = 0; i < 8; ++i) {
            const int row = bm + ty * 8 + i;
            float* cp = C + row * N + bn + tx * 8;
            *(float4*)(cp)     = make_float4(acc[i][0], acc[i][1], acc[i][2], acc[i][3]);
            *(float4*)(cp + 4) = make_float4(acc[i][4], acc[i][5], acc[i][6], acc[i][7]);
        }
    } else {
#pragma unroll
        for (int i = 0; i < 8; ++i) {
            const int m  = bm + ty * 8 + i;
            const int bb = m >> 11;       // / 2048
            const int s  = m & 2047;
#pragma unroll
            for (int jg = 0; jg < 8; jg += 4) {
                const int n0 = bn + tx * 8 + jg;   // multiple of 4, never straddles head
                const int h  = n0 >> 6;
                const int d  = n0 & 63;
                float* cp = C + (((bb * NHEAD + h) * SEQ + s) * HDIM + d);
                *(float4*)cp = make_float4(acc[i][jg], acc[i][jg + 1],
                                           acc[i][jg + 2], acc[i][jg + 3]);
            }
        }
    }
}

// ---------------------------------------------------------------------------
// Flash attention, fp32, causal.  One block = 64 queries of one (b,h).
// 256 threads as 16x16.  Online softmax; stats replicated in registers across
// each 16-lane row group (deterministic shfl reductions keep them consistent).
// smem (dynamic, 64 KB): Qs[64][64], Kt[64][64] (d-major!), Vs[64][64], Ps[64][64]
// ---------------------------------------------------------------------------
__global__ __launch_bounds__(256) void attn_kernel(
    float* __restrict__ Aout,
    const float* __restrict__ Qg, const float* __restrict__ Kg,
    const float* __restrict__ Vg)
{
    extern __shared__ float sm[];
    float* Qs = sm;             // [q][d]
    float* Kt = sm + 4096;      // [d][k]   transposed -> conflict-free S reads
    float* Vs = sm + 8192;      // [k][d]
    float* Ps = sm + 12288;     // [q][k]

    const int tid = threadIdx.x;
    const int tx  = tid & 15;
    const int ty  = tid >> 4;
    const int bh  = blockIdx.y;           // b*16 + h
    const int qt  = blockIdx.x;           // q tile index

    const float* Qp = Qg + (bh * SEQ + qt * 64) * HDIM;

    // load Q tile, pre-scaled by 1/sqrt(64)
#pragma unroll
    for (int p = 0; p < 4; ++p) {
        const int idx = tid * 4 + p * 1024;
        float4 v = *(const float4*)(Qp + idx);
        v.x *= 0.125f; v.y *= 0.125f; v.z *= 0.125f; v.w *= 0.125f;
        *(float4*)(Qs + idx) = v;
    }

    float o[4][4];
    float m_r[4], l_r[4];
#pragma unroll
    for (int i = 0; i < 4; ++i) {
        m_r[i] = -1e30f; l_r[i] = 0.0f;
#pragma unroll
        for (int j = 0; j < 4; ++j) o[i][j] = 0.0f;
    }

    for (int kt = 0; kt <= qt; ++kt) {
        const float* Kp = Kg + (bh * SEQ + kt * 64) * HDIM;
        const float* Vp = Vg + (bh * SEQ + kt * 64) * HDIM;

        __syncthreads();   // previous iteration's Ps/Vs reads done

        // K tile -> smem transposed: Kt[d][k]
        {
            const int kr = tid >> 2;
            const int d0 = (tid & 3) * 16;
#pragma unroll
            for (int c = 0; c < 16; c += 4) {
                float4 v = *(const float4*)(Kp + kr * 64 + d0 + c);
                Kt[(d0 + c + 0) * 64 + kr] = v.x;
                Kt[(d0 + c + 1) * 64 + kr] = v.y;
                Kt[(d0 + c + 2) * 64 + kr] = v.z;
                Kt[(d0 + c + 3) * 64 + kr] = v.w;
            }
        }
        // V tile -> smem natural layout
#pragma unroll
        for (int p = 0; p < 4; ++p) {
            const int idx = tid * 4 + p * 1024;
            *(float4*)(Vs + idx) = *(const float4*)(Vp + idx);
        }
        __syncthreads();

        // ---- S = Q K^T (this thread: rows ty*4+i, cols tx*4+j) ----
        float s[4][4];
#pragma unroll
        for (int i = 0; i < 4; ++i)
#pragma unroll
            for (int j = 0; j < 4; ++j) s[i][j] = 0.0f;

#pragma unroll 4
        for (int d = 0; d < 64; d += 4) {
            float kk[4][4];
#pragma unroll
            for (int dd = 0; dd < 4; ++dd) {
                float4 t = *(const float4*)(Kt + (d + dd) * 64 + tx * 4);
                kk[dd][0] = t.x; kk[dd][1] = t.y; kk[dd][2] = t.z; kk[dd][3] = t.w;
            }
#pragma unroll
            for (int i = 0; i < 4; ++i) {
                float4 t = *(const float4*)(Qs + (ty * 4 + i) * 64 + d);
#pragma unroll
                for (int j = 0; j < 4; ++j)
                    s[i][j] += t.x * kk[0][j] + t.y * kk[1][j]
                             + t.z * kk[2][j] + t.w * kk[3][j];
            }
        }

        // causal mask on the diagonal tile
        if (kt == qt) {
#pragma unroll
            for (int i = 0; i < 4; ++i)
#pragma unroll
                for (int j = 0; j < 4; ++j)
                    if (tx * 4 + j > ty * 4 + i) s[i][j] = -1e30f;
        }

        // ---- online softmax update ----
#pragma unroll
        for (int i = 0; i < 4; ++i) {
            float rm = fmaxf(fmaxf(s[i][0], s[i][1]), fmaxf(s[i][2], s[i][3]));
#pragma unroll
            for (int off = 8; off >= 1; off >>= 1)
                rm = fmaxf(rm, __shfl_xor_sync(0xffffffffu, rm, off));
            const float mn = fmaxf(m_r[i], rm);
            const float p0 = __expf(s[i][0] - mn);
            const float p1 = __expf(s[i][1] - mn);
            const float p2 = __expf(s[i][2] - mn);
            const float p3 = __expf(s[i][3] - mn);
            float rs = (p0 + p1) + (p2 + p3);
#pragma unroll
            for (int off = 8; off >= 1; off >>= 1)
                rs += __shfl_xor_sync(0xffffffffu, rs, off);
            const float f = __expf(m_r[i] - mn);
            l_r[i] = l_r[i] * f + rs;
            m_r[i] = mn;
            o[i][0] *= f; o[i][1] *= f; o[i][2] *= f; o[i][3] *= f;
            *(float4*)(Ps + (ty * 4 + i) * 64 + tx * 4) = make_float4(p0, p1, p2, p3);
        }
        __syncthreads();

        // ---- O += P V (this thread: rows ty*4+i, dims tx*4+j) ----
#pragma unroll 4
        for (int k = 0; k < 64; k += 4) {
            float pv[4][4], vv[4][4];
#pragma unroll
            for (int i = 0; i < 4; ++i) {
                float4 t = *(const float4*)(Ps + (ty * 4 + i) * 64 + k);
                pv[i][0] = t.x; pv[i][1] = t.y; pv[i][2] = t.z; pv[i][3] = t.w;
            }
#pragma unroll
            for (int c = 0; c < 4; ++c) {
                float4 t = *(const float4*)(Vs + (k + c) * 64 + tx * 4);
                vv[c][0] = t.x; vv[c][1] = t.y; vv[c][2] = t.z; vv[c][3] = t.w;
            }
#pragma unroll
            for (int i = 0; i < 4; ++i)
#pragma unroll
                for (int j = 0; j < 4; ++j)
                    o[i][j] += pv[i][0] * vv[0][j] + pv[i][1] * vv[1][j]
                             + pv[i][2] * vv[2][j] + pv[i][3] * vv[3][j];
        }
    }

    // epilogue: normalize and write to [b, s, h*64 + d]
    const int b = bh >> 4;
    const int h = bh & 15;
#pragma unroll
    for (int i = 0; i < 4; ++i) {
        const float inv = 1.0f / l_r[i];
        const int row = b * SEQ + qt * 64 + ty * 4 + i;
        float* op = Aout + row * D_MODEL + h * HDIM + tx * 4;
        *(float4*)op = make_float4(o[i][0] * inv, o[i][1] * inv,
                                   o[i][2] * inv, o[i][3] * inv);
    }
}

// ---------------------------------------------------------------------------
extern "C" void kernel_launch(void* const* d_in, const int* in_sizes, int n_in,
                              void* d_out, int out_size)
{
    const float* x  = (const float*)d_in[0];
    const float* Wq = (const float*)d_in[1];
    const float* Wk = (const float*)d_in[2];
    const float* Wv = (const float*)d_in[3];
    const float* Wo = (const float*)d_in[4];
    float* out = (float*)d_out;

    float *q, *k, *v, *a;
    cudaGetSymbolAddress((void**)&q, g_Q);
    cudaGetSymbolAddress((void**)&k, g_K);
    cudaGetSymbolAddress((void**)&v, g_V);
    cudaGetSymbolAddress((void**)&a, g_A);

    const dim3 gg(D_MODEL / 128, MTOT / 128);   // (8, 32)

    sgemm_nt<<<gg, 256>>>(x, Wq, q, D_MODEL, D_MODEL, 1);
    sgemm_nt<<<gg, 256>>>(x, Wk, k, D_MODEL, D_MODEL, 1);
    sgemm_nt<<<gg, 256>>>(x, Wv, v, D_MODEL, D_MODEL, 1);

    cudaFuncSetAttribute(attn_kernel,
                         cudaFuncAttributeMaxDynamicSharedMemorySize, 65536);
    attn_kernel<<<dim3(SEQ / 64, BATCH * NHEAD), 256, 65536>>>(a, q, k, v);

    sgemm_nt<<<gg, 256>>>(a, Wo, out, D_MODEL, D_MODEL, 0);
}

// round 6
// speedup vs baseline: 1.4822x; 1.4799x over previous
#include <cuda_runtime.h>
#include <cuda_bf16.h>
#include <math.h>
#include <stdint.h>

#define D_MODEL 1024
#define NHEAD   16
#define HDIM    64
#define SEQ     2048
#define BATCH   2
#define MTOT    (BATCH * SEQ)   // 4096
#define KP      3072            // split-bf16 K' = 3*1024
#define TK      64              // bf16 per K chunk (128 bytes)
#define NC      (KP / TK)       // 48 chunks

// ---------------- scratch (static device globals: allocation-free) ----------
__device__ float g_Q[BATCH * NHEAD * SEQ * HDIM];   // [b,h,s,d] fp32
__device__ float g_K[BATCH * NHEAD * SEQ * HDIM];
__device__ float g_V[BATCH * NHEAD * SEQ * HDIM];
__device__ __nv_bfloat16 g_Ax[MTOT * KP];           // split x    [m][3072] (A-mode)
__device__ __nv_bfloat16 g_Bq[D_MODEL * KP];        // split W    [n][3072] (B-mode)
__device__ __nv_bfloat16 g_Bk[D_MODEL * KP];
__device__ __nv_bfloat16 g_Bv[D_MODEL * KP];
__device__ __nv_bfloat16 g_Bo[D_MODEL * KP];
__device__ __nv_bfloat16 g_Aatt[MTOT * KP];         // split attn out (A-mode)

// ============================ helpers ========================================
__device__ __forceinline__ uint32_t smem_u32(const void* p) {
    uint32_t a;
    asm("{ .reg .u64 t; cvta.to.shared.u64 t, %1; cvt.u32.u64 %0, t; }"
        : "=r"(a) : "l"(p));
    return a;
}
__device__ __forceinline__ void ldsm4(uint32_t* r, uint32_t addr) {
    asm volatile("ldmatrix.sync.aligned.m8n8.x4.shared.b16 {%0,%1,%2,%3}, [%4];"
                 : "=r"(r[0]), "=r"(r[1]), "=r"(r[2]), "=r"(r[3]) : "r"(addr));
}
__device__ __forceinline__ void mma16816(float* d, const uint32_t* a,
                                         const uint32_t* b) {
    asm volatile(
        "mma.sync.aligned.m16n8k16.row.col.f32.bf16.bf16.f32 "
        "{%0,%1,%2,%3}, {%4,%5,%6,%7}, {%8,%9}, {%0,%1,%2,%3};"
        : "+f"(d[0]), "+f"(d[1]), "+f"(d[2]), "+f"(d[3])
        : "r"(a[0]), "r"(a[1]), "r"(a[2]), "r"(a[3]), "r"(b[0]), "r"(b[1]));
}

// ============================ split kernel ===================================
// src [rows][1024] fp32 -> dst [rows][3072] bf16
// bmode 0 (A operand): [hi | hi | lo]     bmode 1 (B operand): [hi | lo | hi]
__global__ __launch_bounds__(256) void split_kernel(
    const float* __restrict__ src, __nv_bfloat16* __restrict__ dst, int bmode)
{
    const int idx = blockIdx.x * 256 + threadIdx.x;   // one float4 each
    const int row = idx >> 8;
    const int c   = (idx & 255) * 4;
    float4 v = *(const float4*)(src + (size_t)row * 1024 + c);

    __nv_bfloat16 h0 = __float2bfloat16(v.x), h1 = __float2bfloat16(v.y);
    __nv_bfloat16 h2 = __float2bfloat16(v.z), h3 = __float2bfloat16(v.w);
    __nv_bfloat16 l0 = __float2bfloat16(v.x - __bfloat162float(h0));
    __nv_bfloat16 l1 = __float2bfloat16(v.y - __bfloat162float(h1));
    __nv_bfloat16 l2 = __float2bfloat16(v.z - __bfloat162float(h2));
    __nv_bfloat16 l3 = __float2bfloat16(v.w - __bfloat162float(h3));

    uint2 hu, lu;
    hu.x = ((uint32_t)__bfloat16_as_ushort(h1) << 16) | __bfloat16_as_ushort(h0);
    hu.y = ((uint32_t)__bfloat16_as_ushort(h3) << 16) | __bfloat16_as_ushort(h2);
    lu.x = ((uint32_t)__bfloat16_as_ushort(l1) << 16) | __bfloat16_as_ushort(l0);
    lu.y = ((uint32_t)__bfloat16_as_ushort(l3) << 16) | __bfloat16_as_ushort(l2);

    __nv_bfloat16* p = dst + (size_t)row * KP + c;
    if (bmode) {
        *(uint2*)(p)        = hu;
        *(uint2*)(p + 1024) = lu;
        *(uint2*)(p + 2048) = hu;
    } else {
        *(uint2*)(p)        = hu;
        *(uint2*)(p + 1024) = hu;
        *(uint2*)(p + 2048) = lu;
    }
}

// ============================ mma.sync GEMM ==================================
// C[M=4096, N=1024] = A'[M,3072] @ B'[N,3072]^T  (bf16 in, fp32 accum/out)
// CTA tile 128x128, K-chunk 64 bf16, double-buffered smem (SW128 xor swizzle).
// 8 warps (2 M x 4 N); warp tile 64x32 via m16n8k16 (4 m-frags x 4 n-frags).
// mode 0: C row-major [m][1024].  mode 1: scatter to [b,h,s,d].
#define SMEM_BYTES 65536   // A0(16K) A1(16K) B0(16K) B1(16K)

__device__ __forceinline__ void ldg_tiles(
    const __nv_bfloat16* __restrict__ A, const __nv_bfloat16* __restrict__ B,
    int bm, int bn, int c, int tid, float4* ar, float4* br)
{
#pragma unroll
    for (int j = 0; j < 4; ++j) {
        const int idx = j * 256 + tid, r = idx >> 3, s = idx & 7;
        ar[j] = *(const float4*)(A + (size_t)(bm + r) * KP + c * TK + s * 8);
        br[j] = *(const float4*)(B + (size_t)(bn + r) * KP + c * TK + s * 8);
    }
}
__device__ __forceinline__ void sts_tiles(
    char* smem, uint32_t pa, uint32_t pb, int tid,
    const float4* ar, const float4* br)
{
#pragma unroll
    for (int j = 0; j < 4; ++j) {
        const int idx = j * 256 + tid, r = idx >> 3, s = idx & 7;
        uint32_t off = (uint32_t)(r * 128 + s * 16);
        off ^= (off >> 3) & 0x70;                 // chunk ^= (row & 7)
        *(float4*)(smem + pa + off) = ar[j];
        *(float4*)(smem + pb + off) = br[j];
    }
}

__global__ __launch_bounds__(256) void gemm_mma(
    const __nv_bfloat16* __restrict__ A, const __nv_bfloat16* __restrict__ B,
    float* __restrict__ C, int mode)
{
    extern __shared__ char smem[];
    const uint32_t sbase = smem_u32(smem);
    const int tid  = threadIdx.x;
    const int warp = tid >> 5;
    const int lane = tid & 31;
    const int bm   = blockIdx.y * 128;
    const int bn   = blockIdx.x * 128;
    const int wm   = warp & 1;     // 2 warps in M
    const int wn   = warp >> 1;    // 4 warps in N

    // prologue: chunk0 -> buf0, prefetch chunk1 into regs
    float4 ar[4], br[4];
    ldg_tiles(A, B, bm, bn, 0, tid, ar, br);
    sts_tiles(smem, 0, 32768, tid, ar, br);
    ldg_tiles(A, B, bm, bn, 1, tid, ar, br);
    __syncthreads();

    float acc[4][4][4];
#pragma unroll
    for (int i = 0; i < 4; ++i)
#pragma unroll
        for (int j = 0; j < 4; ++j)
#pragma unroll
            for (int r = 0; r < 4; ++r) acc[i][j][r] = 0.0f;

    // per-lane ldmatrix row terms (within a 128-row, 128B-row tile)
    const int arow = (lane & 7) | ((lane >> 3) & 1) << 3;   // 0..15
    const int ach  = (lane >> 4) & 1;                       // k-chunk select
    uint32_t aterm[4]; int asw[4];
#pragma unroll
    for (int i = 0; i < 4; ++i) {
        const int row = wm * 64 + i * 16 + arow;
        aterm[i] = (uint32_t)(row * 128);
        asw[i]   = row & 7;
    }
    const int q   = lane >> 3;       // matrix index 0..3
    const int bch = q & 1;
    uint32_t bterm[2]; int bsw[2];
#pragma unroll
    for (int jj = 0; jj < 2; ++jj) {
        const int nrow = wn * 32 + jj * 16 + ((q >> 1) << 3) + (lane & 7);
        bterm[jj] = (uint32_t)(nrow * 128);
        bsw[jj]   = nrow & 7;
    }

    for (int c = 0; c < NC; ++c) {
        const int p = c & 1;
        const uint32_t Ab = sbase + (uint32_t)(p * 16384);
        const uint32_t Bb = sbase + 32768u + (uint32_t)(p * 16384);

        if (c + 1 < NC)
            sts_tiles(smem, (uint32_t)((p ^ 1) * 16384),
                      32768u + (uint32_t)((p ^ 1) * 16384), tid, ar, br);

#pragma unroll
        for (int ks = 0; ks < 4; ++ks) {
            const int k2 = ks * 2;
            uint32_t af[4][4], bf[4][2];
#pragma unroll
            for (int i = 0; i < 4; ++i)
                ldsm4(af[i], Ab + aterm[i] + ((uint32_t)((k2 + ach) ^ asw[i]) << 4));
#pragma unroll
            for (int jj = 0; jj < 2; ++jj) {
                uint32_t t[4];
                ldsm4(t, Bb + bterm[jj] + ((uint32_t)((k2 + bch) ^ bsw[jj]) << 4));
                bf[jj * 2 + 0][0] = t[0]; bf[jj * 2 + 0][1] = t[1];
                bf[jj * 2 + 1][0] = t[2]; bf[jj * 2 + 1][1] = t[3];
            }
#pragma unroll
            for (int i = 0; i < 4; ++i)
#pragma unroll
                for (int j = 0; j < 4; ++j)
                    mma16816(acc[i][j], af[i], bf[j]);
        }

        if (c + 2 < NC) ldg_tiles(A, B, bm, bn, c + 2, tid, ar, br);
        __syncthreads();
    }

    // epilogue: direct float2 stores
    const int g   = lane >> 2;
    const int tig = lane & 3;
#pragma unroll
    for (int i = 0; i < 4; ++i) {
#pragma unroll
        for (int j = 0; j < 4; ++j) {
            const int col = bn + wn * 32 + j * 8 + tig * 2;
            const int m0  = bm + wm * 64 + i * 16 + g;
#pragma unroll
            for (int hrow = 0; hrow < 2; ++hrow) {
                const int m = m0 + hrow * 8;
                const float2 v = make_float2(acc[i][j][hrow * 2],
                                             acc[i][j][hrow * 2 + 1]);
                if (mode == 0) {
                    *(float2*)(C + (size_t)m * D_MODEL + col) = v;
                } else {
                    const int b = m >> 11, s2 = m & 2047;
                    const int h = col >> 6, dd = col & 63;
                    *(float2*)(C + ((((size_t)b * NHEAD + h) * SEQ + s2) * HDIM + dd)) = v;
                }
            }
        }
    }
}

// ---------------------------------------------------------------------------
// Flash attention, fp32, causal (validated R3).  Epilogue writes split bf16
// [hi | hi | lo] (A-operand layout) into g_Aatt[m][3072] at cols h*64+tx*4.
// ---------------------------------------------------------------------------
__global__ __launch_bounds__(256) void attn_kernel(
    __nv_bfloat16* __restrict__ Aout,
    const float* __restrict__ Qg, const float* __restrict__ Kg,
    const float* __restrict__ Vg)
{
    extern __shared__ float sm[];
    float* Qs = sm;             // [q][d]
    float* Kt = sm + 4096;      // [d][k]
    float* Vs = sm + 8192;      // [k][d]
    float* Ps = sm + 12288;     // [q][k]

    const int tid = threadIdx.x;
    const int tx  = tid & 15;
    const int ty  = tid >> 4;
    const int bh  = blockIdx.y;
    const int qt  = blockIdx.x;

    const float* Qp = Qg + (bh * SEQ + qt * 64) * HDIM;

#pragma unroll
    for (int p = 0; p < 4; ++p) {
        const int idx = tid * 4 + p * 1024;
        float4 v = *(const float4*)(Qp + idx);
        v.x *= 0.125f; v.y *= 0.125f; v.z *= 0.125f; v.w *= 0.125f;
        *(float4*)(Qs + idx) = v;
    }

    float o[4][4];
    float m_r[4], l_r[4];
#pragma unroll
    for (int i = 0; i < 4; ++i) {
        m_r[i] = -1e30f; l_r[i] = 0.0f;
#pragma unroll
        for (int j = 0; j < 4; ++j) o[i][j] = 0.0f;
    }

    for (int kt = 0; kt <= qt; ++kt) {
        const float* Kp = Kg + (bh * SEQ + kt * 64) * HDIM;
        const float* Vp = Vg + (bh * SEQ + kt * 64) * HDIM;

        __syncthreads();

        {
            const int kr = tid >> 2;
            const int d0 = (tid & 3) * 16;
#pragma unroll
            for (int c = 0; c < 16; c += 4) {
                float4 v = *(const float4*)(Kp + kr * 64 + d0 + c);
                Kt[(d0 + c + 0) * 64 + kr] = v.x;
                Kt[(d0 + c + 1) * 64 + kr] = v.y;
                Kt[(d0 + c + 2) * 64 + kr] = v.z;
                Kt[(d0 + c + 3) * 64 + kr] = v.w;
            }
        }
#pragma unroll
        for (int p = 0; p < 4; ++p) {
            const int idx = tid * 4 + p * 1024;
            *(float4*)(Vs + idx) = *(const float4*)(Vp + idx);
        }
        __syncthreads();

        float s[4][4];
#pragma unroll
        for (int i = 0; i < 4; ++i)
#pragma unroll
            for (int j = 0; j < 4; ++j) s[i][j] = 0.0f;

#pragma unroll 4
        for (int d = 0; d < 64; d += 4) {
            float kk[4][4];
#pragma unroll
            for (int dd = 0; dd < 4; ++dd) {
                float4 t = *(const float4*)(Kt + (d + dd) * 64 + tx * 4);
                kk[dd][0] = t.x; kk[dd][1] = t.y; kk[dd][2] = t.z; kk[dd][3] = t.w;
            }
#pragma unroll
            for (int i = 0; i < 4; ++i) {
                float4 t = *(const float4*)(Qs + (ty * 4 + i) * 64 + d);
#pragma unroll
                for (int j = 0; j < 4; ++j)
                    s[i][j] += t.x * kk[0][j] + t.y * kk[1][j]
                             + t.z * kk[2][j] + t.w * kk[3][j];
            }
        }

        if (kt == qt) {
#pragma unroll
            for (int i = 0; i < 4; ++i)
#pragma unroll
                for (int j = 0; j < 4; ++j)
                    if (tx * 4 + j > ty * 4 + i) s[i][j] = -1e30f;
        }

#pragma unroll
        for (int i = 0; i < 4; ++i) {
            float rm = fmaxf(fmaxf(s[i][0], s[i][1]), fmaxf(s[i][2], s[i][3]));
#pragma unroll
            for (int off = 8; off >= 1; off >>= 1)
                rm = fmaxf(rm, __shfl_xor_sync(0xffffffffu, rm, off));
            const float mn = fmaxf(m_r[i], rm);
            const float p0 = __expf(s[i][0] - mn);
            const float p1 = __expf(s[i][1] - mn);
            const float p2 = __expf(s[i][2] - mn);
            const float p3 = __expf(s[i][3] - mn);
            float rs = (p0 + p1) + (p2 + p3);
#pragma unroll
            for (int off = 8; off >= 1; off >>= 1)
                rs += __shfl_xor_sync(0xffffffffu, rs, off);
            const float f = __expf(m_r[i] - mn);
            l_r[i] = l_r[i] * f + rs;
            m_r[i] = mn;
            o[i][0] *= f; o[i][1] *= f; o[i][2] *= f; o[i][3] *= f;
            *(float4*)(Ps + (ty * 4 + i) * 64 + tx * 4) = make_float4(p0, p1, p2, p3);
        }
        __syncthreads();

#pragma unroll 4
        for (int k = 0; k < 64; k += 4) {
            float pv[4][4], vv[4][4];
#pragma unroll
            for (int i = 0; i < 4; ++i) {
                float4 t = *(const float4*)(Ps + (ty * 4 + i) * 64 + k);
                pv[i][0] = t.x; pv[i][1] = t.y; pv[i][2] = t.z; pv[i][3] = t.w;
            }
#pragma unroll
            for (int c = 0; c < 4; ++c) {
                float4 t = *(const float4*)(Vs + (k + c) * 64 + tx * 4);
                vv[c][0] = t.x; vv[c][1] = t.y; vv[c][2] = t.z; vv[c][3] = t.w;
            }
#pragma unroll
            for (int i = 0; i < 4; ++i)
#pragma unroll
                for (int j = 0; j < 4; ++j)
                    o[i][j] += pv[i][0] * vv[0][j] + pv[i][1] * vv[1][j]
                             + pv[i][2] * vv[2][j] + pv[i][3] * vv[3][j];
        }
    }

    // epilogue: normalize, split hi/lo, write [hi | hi | lo]
    const int b = bh >> 4;
    const int h = bh & 15;
#pragma unroll
    for (int i = 0; i < 4; ++i) {
        const float inv = 1.0f / l_r[i];
        const int rowm = b * SEQ + qt * 64 + ty * 4 + i;
        const float v0 = o[i][0] * inv, v1 = o[i][1] * inv;
        const float v2 = o[i][2] * inv, v3 = o[i][3] * inv;
        __nv_bfloat16 h0 = __float2bfloat16(v0), h1 = __float2bfloat16(v1);
        __nv_bfloat16 h2 = __float2bfloat16(v2), h3 = __float2bfloat16(v3);
        __nv_bfloat16 l0 = __float2bfloat16(v0 - __bfloat162float(h0));
        __nv_bfloat16 l1 = __float2bfloat16(v1 - __bfloat162float(h1));
        __nv_bfloat16 l2 = __float2bfloat16(v2 - __bfloat162float(h2));
        __nv_bfloat16 l3 = __float2bfloat16(v3 - __bfloat162float(h3));
        uint2 hu, lu;
        hu.x = ((uint32_t)__bfloat16_as_ushort(h1) << 16) | __bfloat16_as_ushort(h0);
        hu.y = ((uint32_t)__bfloat16_as_ushort(h3) << 16) | __bfloat16_as_ushort(h2);
        lu.x = ((uint32_t)__bfloat16_as_ushort(l1) << 16) | __bfloat16_as_ushort(l0);
        lu.y = ((uint32_t)__bfloat16_as_ushort(l3) << 16) | __bfloat16_as_ushort(l2);
        __nv_bfloat16* ap = Aout + (size_t)rowm * KP + h * HDIM + tx * 4;
        *(uint2*)(ap)        = hu;
        *(uint2*)(ap + 1024) = hu;
        *(uint2*)(ap + 2048) = lu;
    }
}

// ---------------------------------------------------------------------------
extern "C" void kernel_launch(void* const* d_in, const int* in_sizes, int n_in,
                              void* d_out, int out_size)
{
    const float* x  = (const float*)d_in[0];
    const float* Wq = (const float*)d_in[1];
    const float* Wk = (const float*)d_in[2];
    const float* Wv = (const float*)d_in[3];
    const float* Wo = (const float*)d_in[4];
    float* out = (float*)d_out;

    float *q, *k, *v;
    __nv_bfloat16 *ax, *bq, *bk, *bv, *bo, *aatt;
    cudaGetSymbolAddress((void**)&q,    g_Q);
    cudaGetSymbolAddress((void**)&k,    g_K);
    cudaGetSymbolAddress((void**)&v,    g_V);
    cudaGetSymbolAddress((void**)&ax,   g_Ax);
    cudaGetSymbolAddress((void**)&bq,   g_Bq);
    cudaGetSymbolAddress((void**)&bk,   g_Bk);
    cudaGetSymbolAddress((void**)&bv,   g_Bv);
    cudaGetSymbolAddress((void**)&bo,   g_Bo);
    cudaGetSymbolAddress((void**)&aatt, g_Aatt);

    // split fp32 -> bf16 pairs:  A-operands [hi|hi|lo],  B-operands [hi|lo|hi]
    split_kernel<<<MTOT, 256>>>(x, ax, 0);
    split_kernel<<<D_MODEL, 256>>>(Wq, bq, 1);
    split_kernel<<<D_MODEL, 256>>>(Wk, bk, 1);
    split_kernel<<<D_MODEL, 256>>>(Wv, bv, 1);
    split_kernel<<<D_MODEL, 256>>>(Wo, bo, 1);

    cudaFuncSetAttribute(gemm_mma,
                         cudaFuncAttributeMaxDynamicSharedMemorySize, SMEM_BYTES);
    const dim3 gg(D_MODEL / 128, MTOT / 128);   // (8, 32)

    gemm_mma<<<gg, 256, SMEM_BYTES>>>(ax, bq, q, 1);
    gemm_mma<<<gg, 256, SMEM_BYTES>>>(ax, bk, k, 1);
    gemm_mma<<<gg, 256, SMEM_BYTES>>>(ax, bv, v, 1);

    cudaFuncSetAttribute(attn_kernel,
                         cudaFuncAttributeMaxDynamicSharedMemorySize, 65536);
    attn_kernel<<<dim3(SEQ / 64, BATCH * NHEAD), 256, 65536>>>(aatt, q, k, v);

    gemm_mma<<<gg, 256, SMEM_BYTES>>>(aatt, bo, out, 0);
}